// round 4
// baseline (speedup 1.0000x reference)
#include <cuda_runtime.h>
#include <cuda_bf16.h>

#define BB 128   // batch
#define NN 50    // entities per doc
#define KK 20    // neighbors
#define DD 128   // embedding dim
#define NK (NN*KK)          // 1000
#define BN (BB*NN)          // 6400
#define TOT (BB*NN*KK)      // 128000

// scratch
__device__ float g_att[TOT];       // transposed: att[nk][b]
__device__ float g_ee_dot[BN];
__device__ float g_rel_dot[128];   // R=100, padded
__device__ float g_agg[BN * 2 * DD];  // [bn][256] = [ee | weighted-neighbor-sum]

// ---- packed f32x2 helpers (sm_103a) --------------------------------------
__device__ __forceinline__ unsigned long long pack2(float lo, float hi) {
    unsigned long long r;
    asm("mov.b64 %0, {%1, %2};" : "=l"(r) : "f"(lo), "f"(hi));
    return r;
}
__device__ __forceinline__ void unpack2(unsigned long long v, float& lo, float& hi) {
    asm("mov.b64 {%0, %1}, %2;" : "=f"(lo), "=f"(hi) : "l"(v));
}
__device__ __forceinline__ unsigned long long fma2(unsigned long long a,
                                                   unsigned long long b,
                                                   unsigned long long c) {
    unsigned long long d;
    asm("fma.rn.f32x2 %0, %1, %2, %3;" : "=l"(d) : "l"(a), "l"(b), "l"(c));
    return d;
}

// ---------------------------------------------------------------------------
// Kernel A: rel_dot[r] = dot(rel_emb[r], w2); ee_dot[bn] = dot(ee, w0)
// ---------------------------------------------------------------------------
__global__ __launch_bounds__(256) void k_pre(
    const int* __restrict__ entity_ids,
    const float* __restrict__ ent_emb,
    const float* __restrict__ rel_emb,
    const float* __restrict__ W_att)
{
    int warp = (blockIdx.x * blockDim.x + threadIdx.x) >> 5;
    int lane = threadIdx.x & 31;
    if (warp >= BN + 100) return;

    const float4* row;
    const float4* w;
    if (warp < BN) {
        int eid = entity_ids[warp];
        row = (const float4*)(ent_emb + (size_t)eid * DD);
        w   = (const float4*)(W_att);            // w0
    } else {
        int r = warp - BN;
        row = (const float4*)(rel_emb + (size_t)r * DD);
        w   = (const float4*)(W_att + 2 * DD);   // w2
    }
    float4 a = row[lane], wv = w[lane];
    float s = a.x*wv.x + a.y*wv.y + a.z*wv.z + a.w*wv.w;
    #pragma unroll
    for (int off = 16; off > 0; off >>= 1)
        s += __shfl_xor_sync(0xffffffffu, s, off);
    if (lane == 0) {
        if (warp < BN) g_ee_dot[warp] = s;
        else           g_rel_dot[warp - BN] = s;
    }
}

// ---------------------------------------------------------------------------
// Kernel B: logits (warp per (b,n,k)), stores transposed g_att[nk][b]
// ---------------------------------------------------------------------------
__global__ __launch_bounds__(256) void k_logits(
    const int* __restrict__ entity_ids,
    const int* __restrict__ adj_entity,
    const int* __restrict__ adj_relation,
    const float* __restrict__ ent_emb,
    const float* __restrict__ W_att,
    const float* __restrict__ b_att)
{
    int warp = (blockIdx.x * blockDim.x + threadIdx.x) >> 5;
    int lane = threadIdx.x & 31;

    int b   = warp / NK;
    int rem = warp - b * NK;         // n*KK + k
    int bn  = b * NN + rem / KK;

    int eid = entity_ids[bn];
    int nid = adj_entity[eid * KK + (rem % KK)];
    int rid = adj_relation[eid * KK + (rem % KK)];

    const float4* n4 = (const float4*)(ent_emb + (size_t)nid * DD);
    const float4* w1 = (const float4*)(W_att + DD);

    float4 a = n4[lane], wv = w1[lane];
    float s = a.x*wv.x + a.y*wv.y + a.z*wv.z + a.w*wv.w;
    #pragma unroll
    for (int off = 16; off > 0; off >>= 1)
        s += __shfl_xor_sync(0xffffffffu, s, off);

    if (lane == 0) {
        float v = s + g_ee_dot[bn] + g_rel_dot[rid] + b_att[0];
        g_att[rem * BB + b] = fmaxf(v, 0.0f);
    }
}

// ---------------------------------------------------------------------------
// Kernel C: softmax over batch axis; block per (n,k); coalesced.
// ---------------------------------------------------------------------------
__global__ __launch_bounds__(128) void k_softmax()
{
    int nk = blockIdx.x;
    int b  = threadIdx.x;
    int lane = b & 31, wid = b >> 5;
    __shared__ float red[4];

    float v = g_att[nk * BB + b];

    float m = v;
    #pragma unroll
    for (int off = 16; off > 0; off >>= 1)
        m = fmaxf(m, __shfl_xor_sync(0xffffffffu, m, off));
    if (lane == 0) red[wid] = m;
    __syncthreads();
    m = fmaxf(fmaxf(red[0], red[1]), fmaxf(red[2], red[3]));

    float e = __expf(v - m);
    float s = e;
    #pragma unroll
    for (int off = 16; off > 0; off >>= 1)
        s += __shfl_xor_sync(0xffffffffu, s, off);
    __syncthreads();
    if (lane == 0) red[wid] = s;
    __syncthreads();
    s = red[0] + red[1] + red[2] + red[3];

    g_att[nk * BB + b] = e / s;
}

// ---------------------------------------------------------------------------
// Kernel D1: gather.  One 128-thread block per (b,n); thread = dim d.
// Loads forced into v[20] before the FMA chain -> MLP=20 per thread.
// ---------------------------------------------------------------------------
__global__ __launch_bounds__(128) void k_gather(
    const int* __restrict__ entity_ids,
    const int* __restrict__ adj_entity,
    const float* __restrict__ ent_emb)
{
    __shared__ int   s_nid[KK];
    __shared__ float s_att[KK];

    int bn = blockIdx.x;
    int b  = bn / NN;
    int n  = bn - b * NN;
    int d  = threadIdx.x;

    int eid = entity_ids[bn];
    if (d < KK) {
        s_nid[d] = adj_entity[eid * KK + d];
        s_att[d] = g_att[(n * KK + d) * BB + b];
    }
    __syncthreads();

    float ee = ent_emb[(size_t)eid * DD + d];

    float v[KK];
    #pragma unroll
    for (int k = 0; k < KK; k++)
        v[k] = ent_emb[(size_t)s_nid[k] * DD + d];

    float nb = 0.0f;
    #pragma unroll
    for (int k = 0; k < KK; k++)
        nb = fmaf(s_att[k], v[k], nb);

    g_agg[(size_t)bn * 2 * DD + d]      = ee;
    g_agg[(size_t)bn * 2 * DD + DD + d] = nb;
}

// ---------------------------------------------------------------------------
// Kernel D2: out[6400,128] = relu(agg[6400,256] @ W_conv + b_conv)
// 16 rows per block, 128 threads; thread: 2 outputs (d0,d0+1) x 8 rows,
// packed f32x2 FMA fed from transposed shared tile (broadcast LDS.128).
// ---------------------------------------------------------------------------
#define GROWS  16
#define GPITCH 20     // words per j-row: 80B (16B aligned for rg*8 offsets)

__global__ __launch_bounds__(128) void k_gemm(
    const float* __restrict__ W_conv,
    const float* __restrict__ b_conv,
    float* __restrict__ out)
{
    __shared__ float sT[2 * DD * GPITCH];   // [256][20] = 20 KB

    int t   = threadIdx.x;
    int bn0 = blockIdx.x * GROWS;

    // stage 16x256 tile, transposed: sT[j][row]
    {
        int row = t & 15;          // 0..15
        int jc  = t >> 4;          // 0..7  -> j chunk of 32
        const float4* src = (const float4*)(g_agg + (size_t)(bn0 + row) * 2 * DD + jc * 32);
        #pragma unroll
        for (int c = 0; c < 8; c++) {
            float4 v = src[c];
            int j = jc * 32 + c * 4;
            sT[(j + 0) * GPITCH + row] = v.x;
            sT[(j + 1) * GPITCH + row] = v.y;
            sT[(j + 2) * GPITCH + row] = v.z;
            sT[(j + 3) * GPITCH + row] = v.w;
        }
    }
    __syncthreads();

    int p  = t & 63;          // output pair
    int d0 = 2 * p;
    int rg = t >> 6;          // 0/1 -> rows rg*8 .. rg*8+7

    // acc[o][rp]: output d0+o, row-pair rp (rows rg*8+2*rp, +1) in lo/hi
    unsigned long long acc[2][4];
    {
        unsigned long long i0 = pack2(b_conv[d0],     b_conv[d0]);
        unsigned long long i1 = pack2(b_conv[d0 + 1], b_conv[d0 + 1]);
        #pragma unroll
        for (int rp = 0; rp < 4; rp++) { acc[0][rp] = i0; acc[1][rp] = i1; }
    }

    const float* sb = sT + rg * 8;
    #pragma unroll 4
    for (int j = 0; j < 2 * DD; j++) {
        float2 w = *(const float2*)(W_conv + j * DD + d0);
        unsigned long long w0 = pack2(w.x, w.x);
        unsigned long long w1 = pack2(w.y, w.y);
        float4 sa = *(const float4*)(sb + j * GPITCH);       // rows 0-3 of group
        float4 sc = *(const float4*)(sb + j * GPITCH + 4);   // rows 4-7
        unsigned long long p0 = pack2(sa.x, sa.y);
        unsigned long long p1 = pack2(sa.z, sa.w);
        unsigned long long p2 = pack2(sc.x, sc.y);
        unsigned long long p3 = pack2(sc.z, sc.w);
        acc[0][0] = fma2(p0, w0, acc[0][0]);
        acc[1][0] = fma2(p0, w1, acc[1][0]);
        acc[0][1] = fma2(p1, w0, acc[0][1]);
        acc[1][1] = fma2(p1, w1, acc[1][1]);
        acc[0][2] = fma2(p2, w0, acc[0][2]);
        acc[1][2] = fma2(p2, w1, acc[1][2]);
        acc[0][3] = fma2(p3, w0, acc[0][3]);
        acc[1][3] = fma2(p3, w1, acc[1][3]);
    }

    #pragma unroll
    for (int rp = 0; rp < 4; rp++) {
        float lo0, hi0, lo1, hi1;
        unpack2(acc[0][rp], lo0, hi0);
        unpack2(acc[1][rp], lo1, hi1);
        int r0 = bn0 + rg * 8 + rp * 2;
        float2 o0 = make_float2(fmaxf(lo0, 0.0f), fmaxf(lo1, 0.0f));
        float2 o1 = make_float2(fmaxf(hi0, 0.0f), fmaxf(hi1, 0.0f));
        *(float2*)(out + (size_t)r0 * DD + d0)       = o0;
        *(float2*)(out + (size_t)(r0 + 1) * DD + d0) = o1;
    }
}

// ---------------------------------------------------------------------------
extern "C" void kernel_launch(void* const* d_in, const int* in_sizes, int n_in,
                              void* d_out, int out_size)
{
    const int*   entity_ids = (const int*)  d_in[0];
    const int*   adj_entity = (const int*)  d_in[1];
    const int*   adj_rel    = (const int*)  d_in[2];
    const float* ent_emb    = (const float*)d_in[3];
    const float* rel_emb    = (const float*)d_in[4];
    const float* W_att      = (const float*)d_in[5];
    const float* b_att      = (const float*)d_in[6];
    const float* W_conv     = (const float*)d_in[7];
    const float* b_conv     = (const float*)d_in[8];
    float* out = (float*)d_out;

    k_pre<<<(BN + 100 + 7) / 8, 256>>>(entity_ids, ent_emb, rel_emb, W_att);

    k_logits<<<TOT / 8, 256>>>(entity_ids, adj_entity, adj_rel,
                               ent_emb, W_att, b_att);

    k_softmax<<<NK, 128>>>();

    k_gather<<<BN, 128>>>(entity_ids, adj_entity, ent_emb);

    k_gemm<<<BN / GROWS, 128>>>(W_conv, b_conv, out);
}

// round 5
// speedup vs baseline: 1.1823x; 1.1823x over previous
#include <cuda_runtime.h>
#include <cuda_bf16.h>

#define BB 128   // batch
#define NN 50    // entities per doc
#define KK 20    // neighbors
#define DD 128   // embedding dim
#define NK (NN*KK)          // 1000
#define BN (BB*NN)          // 6400
#define TOT (BB*NN*KK)      // 128000

// scratch
__device__ float g_att[TOT];          // transposed: att[nk][b]
__device__ float g_ee_dot[BN];
__device__ float g_rel_dot[128];      // R=100, padded
__device__ float g_agg[BN * 2 * DD];  // [bn][256] = [ee | weighted-neighbor-sum]

// ---- packed f32x2 helpers (sm_103a) --------------------------------------
__device__ __forceinline__ unsigned long long pack2(float lo, float hi) {
    unsigned long long r;
    asm("mov.b64 %0, {%1, %2};" : "=l"(r) : "f"(lo), "f"(hi));
    return r;
}
__device__ __forceinline__ void unpack2(unsigned long long v, float& lo, float& hi) {
    asm("mov.b64 {%0, %1}, %2;" : "=f"(lo), "=f"(hi) : "l"(v));
}
__device__ __forceinline__ unsigned long long fma2(unsigned long long a,
                                                   unsigned long long b,
                                                   unsigned long long c) {
    unsigned long long d;
    asm("fma.rn.f32x2 %0, %1, %2, %3;" : "=l"(d) : "l"(a), "l"(b), "l"(c));
    return d;
}

// ---------------------------------------------------------------------------
// Kernel A: rel_dot[r] = dot(rel_emb[r], w2); ee_dot[bn] = dot(ee, w0)
// ---------------------------------------------------------------------------
__global__ __launch_bounds__(256) void k_pre(
    const int* __restrict__ entity_ids,
    const float* __restrict__ ent_emb,
    const float* __restrict__ rel_emb,
    const float* __restrict__ W_att)
{
    int warp = (blockIdx.x * blockDim.x + threadIdx.x) >> 5;
    int lane = threadIdx.x & 31;
    if (warp >= BN + 100) return;

    const float4* row;
    const float4* w;
    if (warp < BN) {
        int eid = entity_ids[warp];
        row = (const float4*)(ent_emb + (size_t)eid * DD);
        w   = (const float4*)(W_att);            // w0
    } else {
        int r = warp - BN;
        row = (const float4*)(rel_emb + (size_t)r * DD);
        w   = (const float4*)(W_att + 2 * DD);   // w2
    }
    float4 a = row[lane], wv = w[lane];
    float s = a.x*wv.x + a.y*wv.y + a.z*wv.z + a.w*wv.w;
    #pragma unroll
    for (int off = 16; off > 0; off >>= 1)
        s += __shfl_xor_sync(0xffffffffu, s, off);
    if (lane == 0) {
        if (warp < BN) g_ee_dot[warp] = s;
        else           g_rel_dot[warp - BN] = s;
    }
}

// ---------------------------------------------------------------------------
// Kernel B: logits. One warp per (bn, k-quad): 4 neighbor rows in flight
// (MLP=4), 4 interleaved butterfly reductions, lane0 writes 4 results
// transposed into g_att[nk][b].
// ---------------------------------------------------------------------------
__global__ __launch_bounds__(256) void k_logits(
    const int* __restrict__ entity_ids,
    const int* __restrict__ adj_entity,
    const int* __restrict__ adj_relation,
    const float* __restrict__ ent_emb,
    const float* __restrict__ W_att,
    const float* __restrict__ b_att)
{
    int warp = (blockIdx.x * blockDim.x + threadIdx.x) >> 5;  // 0..TOT/4-1
    int lane = threadIdx.x & 31;

    int bn = warp / 5;
    int k0 = (warp - bn * 5) * 4;     // 0,4,8,12,16
    int b  = bn / NN;
    int n  = bn - b * NN;

    int eid = entity_ids[bn];

    int nid[4], rid[4];
    #pragma unroll
    for (int i = 0; i < 4; i++) {
        nid[i] = adj_entity[eid * KK + k0 + i];
        rid[i] = adj_relation[eid * KK + k0 + i];
    }

    const float4* w1 = (const float4*)(W_att + DD);
    float4 wv = w1[lane];

    float4 v[4];
    #pragma unroll
    for (int i = 0; i < 4; i++)
        v[i] = ((const float4*)(ent_emb + (size_t)nid[i] * DD))[lane];

    float s0 = v[0].x*wv.x + v[0].y*wv.y + v[0].z*wv.z + v[0].w*wv.w;
    float s1 = v[1].x*wv.x + v[1].y*wv.y + v[1].z*wv.z + v[1].w*wv.w;
    float s2 = v[2].x*wv.x + v[2].y*wv.y + v[2].z*wv.z + v[2].w*wv.w;
    float s3 = v[3].x*wv.x + v[3].y*wv.y + v[3].z*wv.z + v[3].w*wv.w;

    #pragma unroll
    for (int off = 16; off > 0; off >>= 1) {
        s0 += __shfl_xor_sync(0xffffffffu, s0, off);
        s1 += __shfl_xor_sync(0xffffffffu, s1, off);
        s2 += __shfl_xor_sync(0xffffffffu, s2, off);
        s3 += __shfl_xor_sync(0xffffffffu, s3, off);
    }

    if (lane == 0) {
        float base = g_ee_dot[bn] + b_att[0];
        float r0 = fmaxf(s0 + base + g_rel_dot[rid[0]], 0.0f);
        float r1 = fmaxf(s1 + base + g_rel_dot[rid[1]], 0.0f);
        float r2 = fmaxf(s2 + base + g_rel_dot[rid[2]], 0.0f);
        float r3 = fmaxf(s3 + base + g_rel_dot[rid[3]], 0.0f);
        float* dst = g_att + (n * KK + k0) * BB + b;
        dst[0 * BB] = r0;
        dst[1 * BB] = r1;
        dst[2 * BB] = r2;
        dst[3 * BB] = r3;
    }
}

// ---------------------------------------------------------------------------
// Kernel C: softmax over batch axis; block per (n,k); coalesced.
// ---------------------------------------------------------------------------
__global__ __launch_bounds__(128) void k_softmax()
{
    int nk = blockIdx.x;
    int b  = threadIdx.x;
    int lane = b & 31, wid = b >> 5;
    __shared__ float red[4];

    float v = g_att[nk * BB + b];

    float m = v;
    #pragma unroll
    for (int off = 16; off > 0; off >>= 1)
        m = fmaxf(m, __shfl_xor_sync(0xffffffffu, m, off));
    if (lane == 0) red[wid] = m;
    __syncthreads();
    m = fmaxf(fmaxf(red[0], red[1]), fmaxf(red[2], red[3]));

    float e = __expf(v - m);
    float s = e;
    #pragma unroll
    for (int off = 16; off > 0; off >>= 1)
        s += __shfl_xor_sync(0xffffffffu, s, off);
    __syncthreads();
    if (lane == 0) red[wid] = s;
    __syncthreads();
    s = red[0] + red[1] + red[2] + red[3];

    g_att[nk * BB + b] = e / s;
}

// ---------------------------------------------------------------------------
// Kernel D1: gather. One 128-thread block per (b,n); thread = dim d.
// Loads forced into v[20] before the FMA chain -> MLP=20 per thread.
// ---------------------------------------------------------------------------
__global__ __launch_bounds__(128) void k_gather(
    const int* __restrict__ entity_ids,
    const int* __restrict__ adj_entity,
    const float* __restrict__ ent_emb)
{
    __shared__ int   s_nid[KK];
    __shared__ float s_att[KK];

    int bn = blockIdx.x;
    int b  = bn / NN;
    int n  = bn - b * NN;
    int d  = threadIdx.x;

    int eid = entity_ids[bn];
    if (d < KK) {
        s_nid[d] = adj_entity[eid * KK + d];
        s_att[d] = g_att[(n * KK + d) * BB + b];
    }
    __syncthreads();

    float ee = ent_emb[(size_t)eid * DD + d];

    float v[KK];
    #pragma unroll
    for (int k = 0; k < KK; k++)
        v[k] = ent_emb[(size_t)s_nid[k] * DD + d];

    float nb = 0.0f;
    #pragma unroll
    for (int k = 0; k < KK; k++)
        nb = fmaf(s_att[k], v[k], nb);

    g_agg[(size_t)bn * 2 * DD + d]      = ee;
    g_agg[(size_t)bn * 2 * DD + DD + d] = nb;
}

// ---------------------------------------------------------------------------
// Kernel D2: out[6400,128] = relu(agg[6400,256] @ W_conv + b_conv)
// 16 rows/block, 128 threads; thread = 2 outputs x 8 rows.
// Shared tile transposed with consecutive rows contiguous -> ulonglong2
// reads give packed row-pairs for fma.rn.f32x2 with ZERO packing MOVs.
// ---------------------------------------------------------------------------
#define GROWS  16
#define GPITCH 20     // floats per j-row: 80B (16B-aligned since 80%16==0)

__global__ __launch_bounds__(128) void k_gemm(
    const float* __restrict__ W_conv,
    const float* __restrict__ b_conv,
    float* __restrict__ out)
{
    __shared__ float sT[2 * DD * GPITCH];   // [256][20] = 20 KB

    int t   = threadIdx.x;
    int bn0 = blockIdx.x * GROWS;

    // stage 16x256 tile, transposed: sT[j][row]
    {
        int row = t & 15;          // 0..15
        int jc  = t >> 4;          // 0..7 -> j chunk of 32
        const float4* src = (const float4*)(g_agg + (size_t)(bn0 + row) * 2 * DD + jc * 32);
        #pragma unroll
        for (int c = 0; c < 8; c++) {
            float4 v = src[c];
            int j = jc * 32 + c * 4;
            sT[(j + 0) * GPITCH + row] = v.x;
            sT[(j + 1) * GPITCH + row] = v.y;
            sT[(j + 2) * GPITCH + row] = v.z;
            sT[(j + 3) * GPITCH + row] = v.w;
        }
    }
    __syncthreads();

    int p  = t & 63;          // output pair index
    int d0 = 2 * p;
    int rg = t >> 6;          // 0/1 -> rows rg*8 .. rg*8+7

    // acc[o][rp]: output d0+o, rows (rg*8+2rp, rg*8+2rp+1) packed lo/hi
    unsigned long long acc[2][4];
    {
        unsigned long long i0 = pack2(b_conv[d0],     b_conv[d0]);
        unsigned long long i1 = pack2(b_conv[d0 + 1], b_conv[d0 + 1]);
        #pragma unroll
        for (int rp = 0; rp < 4; rp++) { acc[0][rp] = i0; acc[1][rp] = i1; }
    }

    const float* sb = sT + rg * 8;
    #pragma unroll 4
    for (int j = 0; j < 2 * DD; j++) {
        float2 w = *(const float2*)(W_conv + j * DD + d0);
        unsigned long long w0 = pack2(w.x, w.x);
        unsigned long long w1 = pack2(w.y, w.y);
        // rows 0..3 and 4..7 of this row-group, already packed in shared
        ulonglong2 pa = *(const ulonglong2*)(sb + j * GPITCH);
        ulonglong2 pb = *(const ulonglong2*)(sb + j * GPITCH + 4);
        acc[0][0] = fma2(pa.x, w0, acc[0][0]);
        acc[1][0] = fma2(pa.x, w1, acc[1][0]);
        acc[0][1] = fma2(pa.y, w0, acc[0][1]);
        acc[1][1] = fma2(pa.y, w1, acc[1][1]);
        acc[0][2] = fma2(pb.x, w0, acc[0][2]);
        acc[1][2] = fma2(pb.x, w1, acc[1][2]);
        acc[0][3] = fma2(pb.y, w0, acc[0][3]);
        acc[1][3] = fma2(pb.y, w1, acc[1][3]);
    }

    #pragma unroll
    for (int rp = 0; rp < 4; rp++) {
        float lo0, hi0, lo1, hi1;
        unpack2(acc[0][rp], lo0, hi0);   // rows r0,r0+1 @ d0
        unpack2(acc[1][rp], lo1, hi1);   // rows r0,r0+1 @ d0+1
        int r0 = bn0 + rg * 8 + rp * 2;
        float2 o0 = make_float2(fmaxf(lo0, 0.0f), fmaxf(lo1, 0.0f));
        float2 o1 = make_float2(fmaxf(hi0, 0.0f), fmaxf(hi1, 0.0f));
        *(float2*)(out + (size_t)r0 * DD + d0)       = o0;
        *(float2*)(out + (size_t)(r0 + 1) * DD + d0) = o1;
    }
}

// ---------------------------------------------------------------------------
extern "C" void kernel_launch(void* const* d_in, const int* in_sizes, int n_in,
                              void* d_out, int out_size)
{
    const int*   entity_ids = (const int*)  d_in[0];
    const int*   adj_entity = (const int*)  d_in[1];
    const int*   adj_rel    = (const int*)  d_in[2];
    const float* ent_emb    = (const float*)d_in[3];
    const float* rel_emb    = (const float*)d_in[4];
    const float* W_att      = (const float*)d_in[5];
    const float* b_att      = (const float*)d_in[6];
    const float* W_conv     = (const float*)d_in[7];
    const float* b_conv     = (const float*)d_in[8];
    float* out = (float*)d_out;

    k_pre<<<(BN + 100 + 7) / 8, 256>>>(entity_ids, ent_emb, rel_emb, W_att);

    // one warp per 4 k-items: TOT/4 warps, 8 warps/block -> 4000 blocks
    k_logits<<<TOT / 4 / 8, 256>>>(entity_ids, adj_entity, adj_rel,
                                   ent_emb, W_att, b_att);

    k_softmax<<<NK, 128>>>();

    k_gather<<<BN, 128>>>(entity_ids, adj_entity, ent_emb);

    k_gemm<<<BN / GROWS, 128>>>(W_conv, b_conv, out);
}